// round 1
// baseline (speedup 1.0000x reference)
#include <cuda_runtime.h>
#include <math.h>

#define B_   4096
#define J_   32
#define E_   256
#define ROWS (B_ * J_)
#define TILE 64
#define KC   32
#define UPITCH 260

#define S_FLOATS   (TILE * E_)      // 16384
#define U_FLOATS   (KC * UPITCH)    // 8320
#define RED_FLOATS (8 * TILE)       // 512
#define INV_FLOATS (TILE)           // 64
#define MAIN_SMEM  ((S_FLOATS + U_FLOATS + RED_FLOATS + INV_FLOATS) * 4)

// Scratch (device globals: allocation-free per harness rules)
__device__ float g_c1[B_ * E_];     // bias + x @ W^T
__device__ float g_c2[J_ * E_];     // keys @ V^T
__device__ float g_gate[B_ * J_];   // sigmoid(x . (s + key))

// ---------------------------------------------------------------------------
// Shared helpers: A-tile load with XOR swizzle, U chunk load (transposed),
// and the 8x8 register microkernel.
//
// A tile layout: s4[r*64 + (f4 ^ ((r>>3)&7))], f4 = k/4. Microkernel lanes
// vary rg=(r>>3) for fixed instruction, so the XOR spreads the 8 addresses
// across all banks (conflict-free LDS.128).
// ---------------------------------------------------------------------------

__device__ __forceinline__ void load_a_tile(const float* __restrict__ A,
                                            int row0, float4* s4, int tid)
{
    #pragma unroll
    for (int it = 0; it < (TILE * E_ / 4) / 256; ++it) {   // 16 iterations
        int idx = tid + 256 * it;
        int r   = idx >> 6;
        int f4  = idx & 63;
        float4 v = reinterpret_cast<const float4*>(A)[(size_t)(row0 + r) * (E_ / 4) + f4];
        s4[(r << 6) + (f4 ^ ((r >> 3) & 7))] = v;
    }
}

// Load W[f][kc0 .. kc0+KC) transposed into u_sm[k*UPITCH + f] (k-major).
__device__ __forceinline__ void load_u_chunk(const float* __restrict__ Wm,
                                             int kc0, float* u_sm, int tid)
{
    #pragma unroll
    for (int it = 0; it < (E_ * KC / 4) / 256; ++it) {     // 8 iterations
        int idx = tid + 256 * it;
        int f   = idx >> 3;
        int k4  = idx & 7;
        float4 v = reinterpret_cast<const float4*>(Wm)[(size_t)f * (E_ / 4) + (kc0 >> 2) + k4];
        int kb = k4 * 4;
        u_sm[(kb + 0) * UPITCH + f] = v.x;
        u_sm[(kb + 1) * UPITCH + f] = v.y;
        u_sm[(kb + 2) * UPITCH + f] = v.z;
        u_sm[(kb + 3) * UPITCH + f] = v.w;
    }
}

__device__ __forceinline__ void mm_chunk(const float4* s4, const float* u_sm,
                                         int kc0, int rg, int cg, float acc[8][8])
{
    #pragma unroll 2
    for (int k0 = 0; k0 < KC; k0 += 4) {
        float4 a[8];
        int f4 = ((kc0 + k0) >> 2) ^ rg;
        #pragma unroll
        for (int i = 0; i < 8; ++i)
            a[i] = s4[((rg * 8 + i) << 6) + f4];
        #pragma unroll
        for (int kk = 0; kk < 4; ++kk) {
            const float* up = u_sm + (k0 + kk) * UPITCH + cg * 8;
            float4 b0 = *reinterpret_cast<const float4*>(up);
            float4 b1 = *reinterpret_cast<const float4*>(up + 4);
            #pragma unroll
            for (int i = 0; i < 8; ++i) {
                float av = (kk == 0) ? a[i].x : (kk == 1) ? a[i].y
                         : (kk == 2) ? a[i].z : a[i].w;
                acc[i][0] += av * b0.x;  acc[i][1] += av * b0.y;
                acc[i][2] += av * b0.z;  acc[i][3] += av * b0.w;
                acc[i][4] += av * b1.x;  acc[i][5] += av * b1.y;
                acc[i][6] += av * b1.z;  acc[i][7] += av * b1.w;
            }
        }
    }
}

// ---------------------------------------------------------------------------
// Kernel: c2[j][f] = sum_e V[f][e] * keys[j][e]
// ---------------------------------------------------------------------------
__global__ void gemm_c2(const float* __restrict__ keys, const float* __restrict__ V)
{
    __shared__ float ks[E_];
    int j = blockIdx.x;
    int f = threadIdx.x;
    ks[f] = keys[j * E_ + f];
    __syncthreads();
    const float4* vp = reinterpret_cast<const float4*>(V) + (size_t)f * (E_ / 4);
    const float4* kp = reinterpret_cast<const float4*>(ks);
    float a = 0.f;
    #pragma unroll
    for (int e4 = 0; e4 < E_ / 4; ++e4) {
        float4 v = vp[e4], k = kp[e4];
        a += v.x * k.x + v.y * k.y + v.z * k.z + v.w * k.w;
    }
    g_c2[j * E_ + f] = a;
}

// ---------------------------------------------------------------------------
// Kernel: c1[b][f] = bias[f] + sum_e W[f][e] * x[b][e]   (tiled GEMM)
// ---------------------------------------------------------------------------
__global__ void __launch_bounds__(256) gemm_c1(const float* __restrict__ x,
                                               const float* __restrict__ W,
                                               const float* __restrict__ bias)
{
    extern __shared__ float sh[];
    float4* s4  = reinterpret_cast<float4*>(sh);
    float* u_sm = sh + S_FLOATS;

    int tid = threadIdx.x;
    int rg = tid & 7, cg = tid >> 3;
    int row0 = blockIdx.x * TILE;

    load_a_tile(x, row0, s4, tid);

    float acc[8][8];
    #pragma unroll
    for (int i = 0; i < 8; ++i)
        #pragma unroll
        for (int jq = 0; jq < 8; ++jq) acc[i][jq] = 0.f;

    for (int c = 0; c < E_ / KC; ++c) {
        __syncthreads();
        load_u_chunk(W, c * KC, u_sm, tid);
        __syncthreads();
        mm_chunk(s4, u_sm, c * KC, rg, cg, acc);
    }

    int f0 = cg * 8;
    float bv[8];
    #pragma unroll
    for (int jq = 0; jq < 8; ++jq) bv[jq] = bias[f0 + jq];
    #pragma unroll
    for (int i = 0; i < 8; ++i) {
        int row = row0 + rg * 8 + i;
        float4 o0 = make_float4(acc[i][0] + bv[0], acc[i][1] + bv[1],
                                acc[i][2] + bv[2], acc[i][3] + bv[3]);
        float4 o1 = make_float4(acc[i][4] + bv[4], acc[i][5] + bv[5],
                                acc[i][6] + bv[6], acc[i][7] + bv[7]);
        float4* op = reinterpret_cast<float4*>(g_c1 + (size_t)row * E_ + f0);
        op[0] = o0; op[1] = o1;
    }
}

// ---------------------------------------------------------------------------
// Kernel: gate[b][j] = sigmoid( dot(x_b, s_bj) + dot(x_b, keys_j) )
// ---------------------------------------------------------------------------
__global__ void __launch_bounds__(256) gate_kernel(const float* __restrict__ x,
                                                   const float* __restrict__ state,
                                                   const float* __restrict__ keys)
{
    __shared__ float4 xs[E_ / 4];
    int b = blockIdx.x, tid = threadIdx.x;
    if (tid < E_ / 4) xs[tid] = reinterpret_cast<const float4*>(x + (size_t)b * E_)[tid];
    __syncthreads();

    int warp = tid >> 5, lane = tid & 31;
    #pragma unroll
    for (int t = 0; t < 4; ++t) {
        int jj = warp + t * 8;
        const float4* sp = reinterpret_cast<const float4*>(state + ((size_t)b * J_ + jj) * E_);
        const float4* kp = reinterpret_cast<const float4*>(keys + (size_t)jj * E_);
        float p = 0.f;
        #pragma unroll
        for (int q = 0; q < 2; ++q) {
            float4 s = sp[lane + 32 * q];
            float4 k = kp[lane + 32 * q];
            float4 xv = xs[lane + 32 * q];
            p += xv.x * (s.x + k.x) + xv.y * (s.y + k.y)
               + xv.z * (s.z + k.z) + xv.w * (s.w + k.w);
        }
        #pragma unroll
        for (int o = 16; o; o >>= 1) p += __shfl_xor_sync(0xffffffffu, p, o);
        if (lane == 0) g_gate[b * J_ + jj] = 1.f / (1.f + expf(-p));
    }
}

// ---------------------------------------------------------------------------
// Main fused kernel: per 64-row tile
//   cand = relu(s@U^T + c1[b] + c2[j]); v = s + gate*cand; out = v/(||v||+1e-8)
// ---------------------------------------------------------------------------
__global__ void __launch_bounds__(256) memcell_main(const float* __restrict__ state,
                                                    const float* __restrict__ U,
                                                    float* __restrict__ out)
{
    extern __shared__ float sh[];
    float4* s4  = reinterpret_cast<float4*>(sh);
    float* u_sm = sh + S_FLOATS;
    float* red  = u_sm + U_FLOATS;
    float* inv  = red + RED_FLOATS;

    int tid = threadIdx.x;
    int rg = tid & 7, cg = tid >> 3;
    int warp = tid >> 5, lane = tid & 31;
    int row0 = blockIdx.x * TILE;

    load_a_tile(state, row0, s4, tid);

    float acc[8][8];
    #pragma unroll
    for (int i = 0; i < 8; ++i)
        #pragma unroll
        for (int jq = 0; jq < 8; ++jq) acc[i][jq] = 0.f;

    for (int c = 0; c < E_ / KC; ++c) {
        __syncthreads();                  // also covers s4 writes on c==0
        load_u_chunk(U, c * KC, u_sm, tid);
        __syncthreads();
        mm_chunk(s4, u_sm, c * KC, rg, cg, acc);
    }

    // Epilogue: add c1 + c2, relu, gate, accumulate row sum-of-squares.
    int f0 = cg * 8;
    float psum[8];
    #pragma unroll
    for (int i = 0; i < 8; ++i) {
        int rl  = rg * 8 + i;
        int rgl = row0 + rl;
        int b   = rgl >> 5;      // J_ == 32
        int jj  = rgl & 31;
        float g = g_gate[rgl];
        const float* c1p = g_c1 + (size_t)b * E_ + f0;
        const float* c2p = g_c2 + (size_t)jj * E_ + f0;

        float4 sa = s4[(rl << 6) + (((f0 >> 2) + 0) ^ rg)];
        float4 sb = s4[(rl << 6) + (((f0 >> 2) + 1) ^ rg)];
        float sv[8] = {sa.x, sa.y, sa.z, sa.w, sb.x, sb.y, sb.z, sb.w};

        float p = 0.f;
        #pragma unroll
        for (int jq = 0; jq < 8; ++jq) {
            float cval = acc[i][jq] + c1p[jq] + c2p[jq];
            cval = fmaxf(cval, 0.f);
            float v = sv[jq] + g * cval;
            p += v * v;
            acc[i][jq] = v;
        }
        psum[i] = p;
    }

    // Cross-thread row reduction: lanes {rg, rg+8, rg+16, rg+24} share rows.
    #pragma unroll
    for (int i = 0; i < 8; ++i) {
        float p = psum[i];
        p += __shfl_xor_sync(0xffffffffu, p, 8);
        p += __shfl_xor_sync(0xffffffffu, p, 16);
        if (lane < 8) red[warp * TILE + lane * 8 + i] = p;
    }
    __syncthreads();
    if (tid < TILE) {
        float s = 0.f;
        #pragma unroll
        for (int w = 0; w < 8; ++w) s += red[w * TILE + tid];
        inv[tid] = 1.f / (sqrtf(s) + 1e-8f);
    }
    __syncthreads();

    #pragma unroll
    for (int i = 0; i < 8; ++i) {
        int rl = rg * 8 + i;
        float sc = inv[rl];
        float4 o0 = make_float4(acc[i][0] * sc, acc[i][1] * sc,
                                acc[i][2] * sc, acc[i][3] * sc);
        float4 o1 = make_float4(acc[i][4] * sc, acc[i][5] * sc,
                                acc[i][6] * sc, acc[i][7] * sc);
        float4* op = reinterpret_cast<float4*>(out + (size_t)(row0 + rl) * E_ + f0);
        op[0] = o0; op[1] = o1;
    }
}

// ---------------------------------------------------------------------------
extern "C" void kernel_launch(void* const* d_in, const int* in_sizes, int n_in,
                              void* d_out, int out_size)
{
    const float* x     = (const float*)d_in[0];
    const float* state = (const float*)d_in[1];
    const float* keys  = (const float*)d_in[2];
    const float* U     = (const float*)d_in[3];
    const float* V     = (const float*)d_in[4];
    const float* W     = (const float*)d_in[5];
    const float* bias  = (const float*)d_in[6];
    float* out = (float*)d_out;

    cudaFuncSetAttribute(gemm_c1,      cudaFuncAttributeMaxDynamicSharedMemorySize, MAIN_SMEM);
    cudaFuncSetAttribute(memcell_main, cudaFuncAttributeMaxDynamicSharedMemorySize, MAIN_SMEM);

    gemm_c2<<<J_, E_>>>(keys, V);
    gemm_c1<<<B_ / TILE, 256, MAIN_SMEM>>>(x, W, bias);
    gate_kernel<<<B_, 256>>>(x, state, keys);
    memcell_main<<<ROWS / TILE, 256, MAIN_SMEM>>>(state, U, out);
}

// round 3
// speedup vs baseline: 2.2998x; 2.2998x over previous
#include <cuda_runtime.h>
#include <math.h>
#include <stdint.h>

#define B_   4096
#define J_   32
#define E_   256
#define ROWS (B_ * J_)

// ======================= scratch (device globals) ==========================
__device__ float g_c1[B_ * E_];     // bias + x @ W^T
__device__ float g_c2[J_ * E_];     // keys @ V^T
__device__ float g_gate[B_ * J_];   // sigmoid(x . (s + key))

// ======================= PTX helpers =======================================
__device__ __forceinline__ uint32_t smem_u32(const void* p) {
    uint32_t a;
    asm("{ .reg .u64 t; cvta.to.shared.u64 t, %1; cvt.u32.u64 %0, t; }"
        : "=r"(a) : "l"(p));
    return a;
}
__device__ __forceinline__ uint32_t tf32u(float x) {   // round-to-nearest tf32
    uint32_t r;
    asm("cvt.rna.tf32.f32 %0, %1;" : "=r"(r) : "f"(x));
    return r;
}

#define CP_ASYNC16(dst, src)                                                  \
    asm volatile("cp.async.cg.shared.global [%0], [%1], 16;"                  \
        :: "r"(dst), "l"(__cvta_generic_to_global((const void*)(src))) : "memory")
#define CP_COMMIT() asm volatile("cp.async.commit_group;" ::: "memory")
#define CP_WAIT1()  asm volatile("cp.async.wait_group 1;" ::: "memory")
#define CP_WAIT0()  asm volatile("cp.async.wait_group 0;" ::: "memory")

__device__ __forceinline__ void mma_tf32(float* d, const uint32_t* a,
                                         const uint32_t* b) {
    asm volatile(
        "mma.sync.aligned.m16n8k8.row.col.f32.tf32.tf32.f32 "
        "{%0,%1,%2,%3}, {%4,%5,%6,%7}, {%8,%9}, {%0,%1,%2,%3};"
        : "+f"(d[0]), "+f"(d[1]), "+f"(d[2]), "+f"(d[3])
        : "r"(a[0]), "r"(a[1]), "r"(a[2]), "r"(a[3]), "r"(b[0]), "r"(b[1]));
}

// ======================= main tensor kernel config =========================
// CTA: 256 thr (8 warps, 2x4), M=128, N=256, K=256 in 8 chunks of 32.
// A resident (pitch 260), B double-buffered (pitch 36). pitch%32==4 =>
// fragment LDS.32 hits all 32 banks.
#define PA 260
#define PB 36
#define BF_F   (128 * PA)            // 33280 floats: B buffers start
#define BSTG_F (256 * PB)            // 9216 floats per stage
#define RED_F  (BF_F + 2 * BSTG_F)   // 51712
#define INV_F  (RED_F + 512)         // 52224
#define SMEM_F (INV_F + 128)         // 52352 floats = 209408 bytes
#define MAIN_SMEM (SMEM_F * 4)

__global__ void __launch_bounds__(256, 1)
memcell_mma(const float* __restrict__ state, const float* __restrict__ U,
            float* __restrict__ out)
{
    extern __shared__ float sm[];
    const int tid  = threadIdx.x;
    const int lane = tid & 31;
    const int wid  = tid >> 5;
    const int grp  = lane >> 2;       // groupID
    const int tig  = lane & 3;        // threadID_in_group
    const int mwarp = wid >> 2;       // 0..1
    const int nwarp = wid & 3;        // 0..3
    const int row0 = blockIdx.x * 128;

    const uint32_t sb = smem_u32(sm);

    // ---- stage A (state tile, full 128x256) via cp.async ----
    #pragma unroll
    for (int i = 0; i < 32; ++i) {
        int idx = tid + (i << 8);
        int r = idx >> 6, c4 = idx & 63;
        CP_ASYNC16(sb + (uint32_t)(r * PA + c4 * 4) * 4u,
                   state + (size_t)(row0 + r) * E_ + c4 * 4);
    }
    // ---- stage B chunk 0 ----
    #pragma unroll
    for (int i = 0; i < 8; ++i) {
        int idx = tid + (i << 8);
        int f = idx >> 3, k4 = idx & 7;
        CP_ASYNC16(sb + (uint32_t)(BF_F + f * PB + k4 * 4) * 4u,
                   U + (size_t)f * E_ + k4 * 4);
    }
    CP_COMMIT();   // G0 = A + B0

    float acc[4][8][4];
    #pragma unroll
    for (int mt = 0; mt < 4; ++mt)
        #pragma unroll
        for (int nt = 0; nt < 8; ++nt)
            #pragma unroll
            for (int q = 0; q < 4; ++q) acc[mt][nt][q] = 0.f;

    // ---- mainloop over 8 K-chunks of 32, B double-buffered ----
    #pragma unroll 1
    for (int c = 0; c < 8; ++c) {
        __syncthreads();   // readers of stage (c+1)&1 (iter c-1) are done
        if (c + 1 < 8) {
            uint32_t bst = sb + (uint32_t)(BF_F + ((c + 1) & 1) * BSTG_F) * 4u;
            #pragma unroll
            for (int i = 0; i < 8; ++i) {
                int idx = tid + (i << 8);
                int f = idx >> 3, k4 = idx & 7;
                CP_ASYNC16(bst + (uint32_t)(f * PB + k4 * 4) * 4u,
                           U + (size_t)f * E_ + (c + 1) * 32 + k4 * 4);
            }
            CP_COMMIT();
            CP_WAIT1();    // chunk c landed; chunk c+1 pending
        } else {
            CP_WAIT0();
        }
        __syncthreads();

        const float* Bb = sm + BF_F + (c & 1) * BSTG_F;
        #pragma unroll
        for (int ks = 0; ks < 4; ++ks) {
            const int kb = ks * 8 + tig;
            uint32_t afr[4][4];
            #pragma unroll
            for (int mt = 0; mt < 4; ++mt) {
                const float* ap = sm + (mwarp * 64 + mt * 16 + grp) * PA
                                     + c * 32 + kb;
                afr[mt][0] = tf32u(ap[0]);
                afr[mt][1] = tf32u(ap[8 * PA]);
                afr[mt][2] = tf32u(ap[4]);
                afr[mt][3] = tf32u(ap[8 * PA + 4]);
            }
            uint32_t bfr[8][2];
            #pragma unroll
            for (int nt = 0; nt < 8; ++nt) {
                const float* bp = Bb + (nwarp * 64 + nt * 8 + grp) * PB + kb;
                bfr[nt][0] = tf32u(bp[0]);
                bfr[nt][1] = tf32u(bp[4]);
            }
            #pragma unroll
            for (int mt = 0; mt < 4; ++mt)
                #pragma unroll
                for (int nt = 0; nt < 8; ++nt)
                    mma_tf32(acc[mt][nt], afr[mt], bfr[nt]);
        }
    }

    __syncthreads();   // all mma smem reads done before v overwrites A

    // ---- epilogue pass 1: v = s + gate*relu(acc + c1 + c2) -> A smem ----
    float* red = sm + RED_F;
    float* inv = sm + INV_F;
    #pragma unroll
    for (int mt = 0; mt < 4; ++mt) {
        #pragma unroll
        for (int r2 = 0; r2 < 2; ++r2) {
            int rl   = mwarp * 64 + mt * 16 + grp + r2 * 8;
            int grow = row0 + rl;
            float gv = g_gate[grow];
            const float* c1r = g_c1 + (size_t)(grow >> 5) * E_;
            const float* c2r = g_c2 + (size_t)(grow & 31) * E_;
            float ss = 0.f;
            #pragma unroll
            for (int nt = 0; nt < 8; ++nt) {
                int col = nwarp * 64 + nt * 8 + tig * 2;
                float2 sv  = *reinterpret_cast<float2*>(sm + rl * PA + col);
                float2 c1v = *reinterpret_cast<const float2*>(c1r + col);
                float2 c2v = *reinterpret_cast<const float2*>(c2r + col);
                float d0 = acc[mt][nt][r2 * 2 + 0] + c1v.x + c2v.x;
                float d1 = acc[mt][nt][r2 * 2 + 1] + c1v.y + c2v.y;
                float v0 = sv.x + gv * fmaxf(d0, 0.f);
                float v1 = sv.y + gv * fmaxf(d1, 0.f);
                ss += v0 * v0 + v1 * v1;
                *reinterpret_cast<float2*>(sm + rl * PA + col) = make_float2(v0, v1);
            }
            ss += __shfl_xor_sync(0xffffffffu, ss, 1);
            ss += __shfl_xor_sync(0xffffffffu, ss, 2);
            if (tig == 0) red[rl * 4 + nwarp] = ss;
        }
    }
    __syncthreads();
    if (tid < 128) {
        float s = red[tid * 4] + red[tid * 4 + 1]
                + red[tid * 4 + 2] + red[tid * 4 + 3];
        inv[tid] = 1.f / (sqrtf(s) + 1e-8f);
    }
    __syncthreads();

    // ---- epilogue pass 2: coalesced normalized writeback ----
    #pragma unroll
    for (int i = 0; i < 32; ++i) {
        int idx = tid + (i << 8);
        int r = idx >> 6, c4 = idx & 63;
        float iv = inv[r];
        float4 v = *reinterpret_cast<float4*>(sm + r * PA + c4 * 4);
        v.x *= iv; v.y *= iv; v.z *= iv; v.w *= iv;
        reinterpret_cast<float4*>(out + (size_t)(row0 + r) * E_)[c4] = v;
    }
}

// ======================= R1 scalar kernels (c1 / c2 / gate) ================
#define TILE 64
#define KC   32
#define UPITCH 260
#define S_FLOATS   (TILE * E_)
#define U_FLOATS   (KC * UPITCH)
#define C1_SMEM    ((S_FLOATS + U_FLOATS) * 4)

__device__ __forceinline__ void load_a_tile(const float* __restrict__ A,
                                            int row0, float4* s4, int tid)
{
    #pragma unroll
    for (int it = 0; it < (TILE * E_ / 4) / 256; ++it) {
        int idx = tid + 256 * it;
        int r   = idx >> 6;
        int f4  = idx & 63;
        float4 vv = reinterpret_cast<const float4*>(A)[(size_t)(row0 + r) * (E_ / 4) + f4];
        s4[(r << 6) + (f4 ^ ((r >> 3) & 7))] = vv;
    }
}

__device__ __forceinline__ void load_u_chunk(const float* __restrict__ Wm,
                                             int kc0, float* u_sm, int tid)
{
    #pragma unroll
    for (int it = 0; it < (E_ * KC / 4) / 256; ++it) {
        int idx = tid + 256 * it;
        int f   = idx >> 3;
        int k4  = idx & 7;
        float4 vv = reinterpret_cast<const float4*>(Wm)[(size_t)f * (E_ / 4) + (kc0 >> 2) + k4];
        int kb = k4 * 4;
        u_sm[(kb + 0) * UPITCH + f] = vv.x;
        u_sm[(kb + 1) * UPITCH + f] = vv.y;
        u_sm[(kb + 2) * UPITCH + f] = vv.z;
        u_sm[(kb + 3) * UPITCH + f] = vv.w;
    }
}

__device__ __forceinline__ void mm_chunk(const float4* s4, const float* u_sm,
                                         int kc0, int rg, int cg, float acc[8][8])
{
    #pragma unroll 2
    for (int k0 = 0; k0 < KC; k0 += 4) {
        float4 a[8];
        int f4 = ((kc0 + k0) >> 2) ^ rg;
        #pragma unroll
        for (int i = 0; i < 8; ++i)
            a[i] = s4[((rg * 8 + i) << 6) + f4];
        #pragma unroll
        for (int kk = 0; kk < 4; ++kk) {
            const float* up = u_sm + (k0 + kk) * UPITCH + cg * 8;
            float4 b0 = *reinterpret_cast<const float4*>(up);
            float4 b1 = *reinterpret_cast<const float4*>(up + 4);
            #pragma unroll
            for (int i = 0; i < 8; ++i) {
                float av = (kk == 0) ? a[i].x : (kk == 1) ? a[i].y
                         : (kk == 2) ? a[i].z : a[i].w;
                acc[i][0] += av * b0.x;  acc[i][1] += av * b0.y;
                acc[i][2] += av * b0.z;  acc[i][3] += av * b0.w;
                acc[i][4] += av * b1.x;  acc[i][5] += av * b1.y;
                acc[i][6] += av * b1.z;  acc[i][7] += av * b1.w;
            }
        }
    }
}

__global__ void gemm_c2(const float* __restrict__ keys, const float* __restrict__ V)
{
    __shared__ float ks[E_];
    int j = blockIdx.x;
    int f = threadIdx.x;
    ks[f] = keys[j * E_ + f];
    __syncthreads();
    const float4* vp = reinterpret_cast<const float4*>(V) + (size_t)f * (E_ / 4);
    const float4* kp = reinterpret_cast<const float4*>(ks);
    float a = 0.f;
    #pragma unroll
    for (int e4 = 0; e4 < E_ / 4; ++e4) {
        float4 vv = vp[e4], k = kp[e4];
        a += vv.x * k.x + vv.y * k.y + vv.z * k.z + vv.w * k.w;
    }
    g_c2[j * E_ + f] = a;
}

__global__ void __launch_bounds__(256) gemm_c1(const float* __restrict__ x,
                                               const float* __restrict__ W,
                                               const float* __restrict__ bias)
{
    extern __shared__ float sh[];
    float4* s4  = reinterpret_cast<float4*>(sh);
    float* u_sm = sh + S_FLOATS;

    int tid = threadIdx.x;
    int rg = tid & 7, cg = tid >> 3;
    int row0 = blockIdx.x * TILE;

    load_a_tile(x, row0, s4, tid);

    float acc[8][8];
    #pragma unroll
    for (int i = 0; i < 8; ++i)
        #pragma unroll
        for (int jq = 0; jq < 8; ++jq) acc[i][jq] = 0.f;

    for (int c = 0; c < E_ / KC; ++c) {
        __syncthreads();
        load_u_chunk(W, c * KC, u_sm, tid);
        __syncthreads();
        mm_chunk(s4, u_sm, c * KC, rg, cg, acc);
    }

    int f0 = cg * 8;
    float bv[8];
    #pragma unroll
    for (int jq = 0; jq < 8; ++jq) bv[jq] = bias[f0 + jq];
    #pragma unroll
    for (int i = 0; i < 8; ++i) {
        int row = row0 + rg * 8 + i;
        float4 o0 = make_float4(acc[i][0] + bv[0], acc[i][1] + bv[1],
                                acc[i][2] + bv[2], acc[i][3] + bv[3]);
        float4 o1 = make_float4(acc[i][4] + bv[4], acc[i][5] + bv[5],
                                acc[i][6] + bv[6], acc[i][7] + bv[7]);
        float4* op2 = reinterpret_cast<float4*>(g_c1 + (size_t)row * E_ + f0);
        op2[0] = o0; op2[1] = o1;
    }
}

__global__ void __launch_bounds__(256) gate_kernel(const float* __restrict__ x,
                                                   const float* __restrict__ state,
                                                   const float* __restrict__ keys)
{
    __shared__ float4 xs[E_ / 4];
    int b = blockIdx.x, tid = threadIdx.x;
    if (tid < E_ / 4) xs[tid] = reinterpret_cast<const float4*>(x + (size_t)b * E_)[tid];
    __syncthreads();

    int warp = tid >> 5, lane = tid & 31;
    #pragma unroll
    for (int t = 0; t < 4; ++t) {
        int jj = warp + t * 8;
        const float4* sp = reinterpret_cast<const float4*>(state + ((size_t)b * J_ + jj) * E_);
        const float4* kp = reinterpret_cast<const float4*>(keys + (size_t)jj * E_);
        float p = 0.f;
        #pragma unroll
        for (int q = 0; q < 2; ++q) {
            float4 s = sp[lane + 32 * q];
            float4 k = kp[lane + 32 * q];
            float4 xv = xs[lane + 32 * q];
            p += xv.x * (s.x + k.x) + xv.y * (s.y + k.y)
               + xv.z * (s.z + k.z) + xv.w * (s.w + k.w);
        }
        #pragma unroll
        for (int o = 16; o; o >>= 1) p += __shfl_xor_sync(0xffffffffu, p, o);
        if (lane == 0) g_gate[b * J_ + jj] = 1.f / (1.f + expf(-p));
    }
}

// ===========================================================================
extern "C" void kernel_launch(void* const* d_in, const int* in_sizes, int n_in,
                              void* d_out, int out_size)
{
    const float* x     = (const float*)d_in[0];
    const float* state = (const float*)d_in[1];
    const float* keys  = (const float*)d_in[2];
    const float* U     = (const float*)d_in[3];
    const float* V     = (const float*)d_in[4];
    const float* W     = (const float*)d_in[5];
    const float* bias  = (const float*)d_in[6];
    float* out = (float*)d_out;

    cudaFuncSetAttribute(gemm_c1,     cudaFuncAttributeMaxDynamicSharedMemorySize, C1_SMEM);
    cudaFuncSetAttribute(memcell_mma, cudaFuncAttributeMaxDynamicSharedMemorySize, MAIN_SMEM);

    gemm_c2<<<J_, E_>>>(keys, V);
    gemm_c1<<<B_ / TILE, 256, C1_SMEM>>>(x, W, bias);
    gate_kernel<<<B_, 256>>>(x, state, keys);
    memcell_mma<<<ROWS / 128, 256, MAIN_SMEM>>>(state, U, out);
}